// round 9
// baseline (speedup 1.0000x reference)
#include <cuda_runtime.h>
#include <cuda_bf16.h>
#include <cstdint>
#include <cstddef>
#include <math.h>

#define Bb 32
#define Tt 1024
#define Dd 512
#define Hh 512
#define R4 4096
#define NBLK 128
#define NTHR 256

__device__ float    g_P[(size_t)Tt * R4 * Bb];   // [t][r][b], r = cell*2048+gate*512+j
__device__ float    g_H[2][2][Hh/4][Bb][4];      // [pp][cell][j/4][b][j&3]
__device__ float    g_XH[2][Tt][Bb];
__device__ unsigned g_bar;

// HMMA fragment banks (packed exactly in mma.sync m16n8k16 register layout)
__device__ unsigned g_Wfh[2][128][32][32][4];    // [cell][mtile][ktile][lane][areg] hi
__device__ unsigned g_Wfl[2][128][32][32][4];    // lo
__device__ unsigned g_Ufh[Tt][32][4][32][2];     // [t][ktile][ntile][lane][breg] hi
__device__ unsigned g_Ufl[Tt][32][4][32][2];     // lo

__device__ __forceinline__ float fsig(float x) {
    x = fminf(fmaxf(x, -30.0f), 30.0f);
    return __fdividef(1.0f, 1.0f + __expf(-x));
}
__device__ __forceinline__ float ftanh(float x) {
    x = fminf(fmaxf(x, -15.0f), 15.0f);
    float e = __expf(2.0f * x);
    return __fdividef(e - 1.0f, e + 1.0f);
}
__device__ __forceinline__ float4 ldcg4(const float4* p) {
    float4 v;
    asm volatile("ld.global.cg.v4.f32 {%0,%1,%2,%3},[%4];"
                 : "=f"(v.x), "=f"(v.y), "=f"(v.z), "=f"(v.w) : "l"(p));
    return v;
}
__device__ __forceinline__ void stcg2(float2* p, float2 v) {
    asm volatile("st.global.cg.v2.f32 [%0],{%1,%2};" :: "l"(p), "f"(v.x), "f"(v.y));
}
__device__ __forceinline__ float ldcg1(const float* p) {
    float v; asm volatile("ld.global.cg.f32 %0,[%1];" : "=f"(v) : "l"(p)); return v;
}
// split x into bf16 hi + bf16 lo (x ≈ hi + lo, error ~2^-24 relative)
__device__ __forceinline__ void split2(float x0, float x1, unsigned& h, unsigned& l) {
    __nv_bfloat16 h0 = __float2bfloat16(x0), h1 = __float2bfloat16(x1);
    __nv_bfloat16 l0 = __float2bfloat16(x0 - __bfloat162float(h0));
    __nv_bfloat16 l1 = __float2bfloat16(x1 - __bfloat162float(h1));
    h = (unsigned)__bfloat16_as_ushort(h0) | ((unsigned)__bfloat16_as_ushort(h1) << 16);
    l = (unsigned)__bfloat16_as_ushort(l0) | ((unsigned)__bfloat16_as_ushort(l1) << 16);
}
__device__ __forceinline__ void mma16816(float* c, uint4 a, uint2 b) {
    asm volatile("mma.sync.aligned.m16n8k16.row.col.f32.bf16.bf16.f32 "
                 "{%0,%1,%2,%3},{%4,%5,%6,%7},{%8,%9},{%0,%1,%2,%3};"
                 : "+f"(c[0]), "+f"(c[1]), "+f"(c[2]), "+f"(c[3])
                 : "r"(a.x), "r"(a.y), "r"(a.z), "r"(a.w), "r"(b.x), "r"(b.y));
}

// =====================================================================
// convW: Wih -> split-bf16 A-fragments. a0=(g,k0) a1=(g+8,k0) a2=(g,k0+8) a3=(g+8,k0+8)
// =====================================================================
__global__ __launch_bounds__(256) void convW_kernel(
    const float* __restrict__ wf, const float* __restrict__ wb)
{
    int idx  = blockIdx.x * 256 + threadIdx.x;     // 2*128*32*32 = 262144
    int lane = idx & 31, kt = (idx >> 5) & 31, mt = (idx >> 10) & 127, cell = idx >> 17;
    const float* w = cell ? wb : wf;
    int g = lane >> 2, tig = lane & 3;
    int k0 = kt * 16 + 2 * tig;
    int r0 = mt * 16 + g;
    unsigned h[4], l[4];
#pragma unroll
    for (int i = 0; i < 4; ++i) {
        int r = r0 + (i & 1) * 8;
        int k = k0 + (i >> 1) * 8;
        split2(w[(size_t)r * Dd + k], w[(size_t)r * Dd + k + 1], h[i], l[i]);
    }
    *(uint4*)&g_Wfh[cell][mt][kt][lane][0] = make_uint4(h[0], h[1], h[2], h[3]);
    *(uint4*)&g_Wfl[cell][mt][kt][lane][0] = make_uint4(l[0], l[1], l[2], l[3]);
}

// =====================================================================
// convU: U -> split-bf16 B-fragments. b0=(k0,col g) b1=(k0+8,col g)
// =====================================================================
__global__ __launch_bounds__(256) void convU_kernel(const float* __restrict__ U)
{
    int idx  = blockIdx.x * 256 + threadIdx.x;     // 1024*32*4*32 = 4194304
    int lane = idx & 31, nt = (idx >> 5) & 3, kt = (idx >> 7) & 31, t = idx >> 12;
    int g = lane >> 2, tig = lane & 3;
    int b = nt * 8 + g;
    int k0 = kt * 16 + 2 * tig;
    const float* up = &U[(size_t)b * (Tt * Dd) + (size_t)t * Dd];
    unsigned h0, l0, h1, l1;
    split2(up[k0],     up[k0 + 1], h0, l0);
    split2(up[k0 + 8], up[k0 + 9], h1, l1);
    *(uint2*)&g_Ufh[t][kt][nt][lane][0] = make_uint2(h0, h1);
    *(uint2*)&g_Ufl[t][kt][nt][lane][0] = make_uint2(l0, l1);
}

// =====================================================================
// pre_mma: P[t][r][b] = Wih@u + bih + bhh via 3-term split-bf16 HMMA.
// grid (32 rowblocks, 1024 t) x 256 thr; warp = 16 rows x 32 batch.
// =====================================================================
__global__ __launch_bounds__(256) void pre_mma_kernel(
    const float* __restrict__ bih_f, const float* __restrict__ bhh_f,
    const float* __restrict__ bih_b, const float* __restrict__ bhh_b)
{
    const int t    = blockIdx.y;
    const int rb   = blockIdx.x;
    const int warp = threadIdx.x >> 5;
    const int lane = threadIdx.x & 31;
    const int mg   = rb * 8 + warp;        // 0..255
    const int cell = mg >> 7;
    const int mt   = mg & 127;
    const int g    = lane >> 2, tig = lane & 3;

    float acc[4][4];
#pragma unroll
    for (int n = 0; n < 4; ++n)
#pragma unroll
        for (int i = 0; i < 4; ++i) acc[n][i] = 0.0f;

    const uint4* Ah = (const uint4*)&g_Wfh[cell][mt][0][lane][0];   // +kt*32 uint4
    const uint4* Al = (const uint4*)&g_Wfl[cell][mt][0][lane][0];
    const uint2* Bh = (const uint2*)&g_Ufh[t][0][0][lane][0];       // +(kt*4+nt)*32 uint2
    const uint2* Bl = (const uint2*)&g_Ufl[t][0][0][lane][0];

#pragma unroll 2
    for (int kt = 0; kt < 32; ++kt) {
        uint4 ah = Ah[kt * 32];
        uint4 al = Al[kt * 32];
#pragma unroll
        for (int nt = 0; nt < 4; ++nt) {
            uint2 bh = Bh[kt * 128 + nt * 32];
            uint2 bl = Bl[kt * 128 + nt * 32];
            mma16816(acc[nt], ah, bh);   // hi*hi
            mma16816(acc[nt], ah, bl);   // hi*lo
            mma16816(acc[nt], al, bh);   // lo*hi
        }
    }

    const int rw0 = mt * 16 + g;           // within-cell row
    const float* bi = cell ? bih_b : bih_f;
    const float* bh = cell ? bhh_b : bhh_f;
    const float bias0 = bi[rw0] + bh[rw0];
    const float bias1 = bi[rw0 + 8] + bh[rw0 + 8];
    const size_t rowbase = ((size_t)t * R4 + (size_t)cell * 2048 + rw0) * Bb;
#pragma unroll
    for (int nt = 0; nt < 4; ++nt) {
        int col = nt * 8 + 2 * tig;
        *(float2*)&g_P[rowbase + col] =
            make_float2(acc[nt][0] + bias0, acc[nt][1] + bias0);
        *(float2*)&g_P[rowbase + (size_t)8 * Bb + col] =
            make_float2(acc[nt][2] + bias1, acc[nt][3] + bias1);
    }
}

// =====================================================================
// Kernel 2: persistent recurrence (unchanged — near its floor).
// =====================================================================
__global__ void __launch_bounds__(NTHR, 1) rec_kernel(
    const float* __restrict__ whh_f, const float* __restrict__ whh_b,
    const float* __restrict__ wih_f, const float* __restrict__ wih_b)
{
    extern __shared__ char smraw[];
    float*  ws   = (float*)smraw;                 // [32 rows][512]  row = p*8+u*4+gate
    float4* hs   = (float4*)(smraw + 65536);      // [128 kq][32 b]
    float*  redA = (float*)(smraw + 131072);      // [8 w][8 q][32 b]
    float*  rsum = redA + 8*8*32;                 // [32]
    float*  red  = rsum + 32;                     // [256]

    const int tid  = threadIdx.x;
    const int w    = tid >> 5;
    const int p    = w & 3;
    const int kh   = w >> 2;
    const int b    = tid & 31;
    const int cell = blockIdx.x >> 6;
    const int g    = blockIdx.x & 63;
    const int jA   = g * 8 + 2 * p;

    const float* whh = cell ? whh_b : whh_f;
    const float* wih = cell ? wih_b : wih_f;

    for (int idx = tid * 4; idx < 32 * 512; idx += NTHR * 4) {
        int rl = idx >> 9, k = idx & 511;
        int p_ = rl >> 3, q = rl & 7, u = q >> 2, gate = q & 3;
        int grow = gate * 512 + g * 8 + 2 * p_ + u;
        *(float4*)&ws[idx] = *(const float4*)&whh[(size_t)grow * 512 + k];
    }
    {   // rowsums of Wih (sub-step-2 scalar-broadcast projection)
        int rl = tid & 31, part = tid >> 5;
        int p_ = rl >> 3, q = rl & 7, u = q >> 2, gate = q & 3;
        int grow = gate * 512 + g * 8 + 2 * p_ + u;
        float s = 0.0f;
        const float* pp = &wih[(size_t)grow * 512 + part * 64];
#pragma unroll 4
        for (int k = 0; k < 64; k += 4) {
            float4 v = *(const float4*)&pp[k];
            s += v.x + v.y + v.z + v.w;
        }
        red[tid] = s;
    }
    __syncthreads();
    if (tid < 32) {
        float s = 0.0f;
#pragma unroll
        for (int q = 0; q < 8; ++q) s += red[tid + 32 * q];
        rsum[tid] = s;
    }
    __syncthreads();
    float rs[8];
#pragma unroll
    for (int q = 0; q < 8; ++q) rs[q] = rsum[p * 8 + q];

    float cst[2] = {0.0f, 0.0f};
    const float4* wr4 = (const float4*)(ws + (p * 8) * 512);
    const bool is_xh = (cell == 1 && jA + 1 == Hh - 1);

    for (int step = 0; step < 2 * Tt; ++step) {
        const int t = step >> 1, sub = step & 1;
        const int rbuf = step & 1, wbuf = rbuf ^ 1;

        float pv[8];
        if (kh == 0) {
            const float* Pt = g_P + ((size_t)t * R4 + (size_t)cell * 2048) * Bb;
#pragma unroll
            for (int q = 0; q < 8; ++q) {
                int u = q >> 2, gate = q & 3;
                pv[q] = Pt[(size_t)(gate * 512 + jA + u) * Bb + b];
            }
        }
        float xh = (sub && kh == 0) ? ldcg1(&g_H[rbuf][1][(Hh - 1) >> 2][b][3]) : 0.0f;

        if (step == 0) {
            float4 z = make_float4(0.f, 0.f, 0.f, 0.f);
            for (int i = tid; i < 128 * 32; i += NTHR) hs[i] = z;
        } else {
            const float4* src = (const float4*)&g_H[rbuf][cell][0][0][0];
            for (int i = tid; i < 128 * 32; i += NTHR) hs[i] = ldcg4(&src[i]);
        }
        __syncthreads();

        float acc[8];
#pragma unroll
        for (int q = 0; q < 8; ++q) acc[q] = 0.0f;
        const float4* hb = hs + b;
#pragma unroll 4
        for (int kq = kh * 64; kq < kh * 64 + 64; ++kq) {
            float4 hv = hb[kq * 32];
#pragma unroll
            for (int q = 0; q < 8; ++q) {
                float4 wv = wr4[q * 128 + kq];
                acc[q] += wv.x * hv.x;
                acc[q] += wv.y * hv.y;
                acc[q] += wv.z * hv.z;
                acc[q] += wv.w * hv.w;
            }
        }
#pragma unroll
        for (int q = 0; q < 8; ++q) redA[(w * 8 + q) * 32 + b] = acc[q];
        __syncthreads();

        if (kh == 0) {
            float h2v[2];
#pragma unroll
            for (int u = 0; u < 2; ++u) {
#pragma unroll
                for (int q = 0; q < 4; ++q) {
                    int qq = u * 4 + q;
                    acc[qq] += redA[((w + 4) * 8 + qq) * 32 + b];
                    acc[qq] += pv[qq] + xh * rs[qq];
                }
                float iv = acc[u*4+0], fv = acc[u*4+1], gv = acc[u*4+2], ov = acc[u*4+3];
                cst[u] = fsig(fv) * cst[u] + fsig(iv) * ftanh(gv);
                h2v[u] = fsig(ov) * ftanh(cst[u]);
            }
            stcg2((float2*)&g_H[wbuf][cell][jA >> 2][b][jA & 3],
                  make_float2(h2v[0], h2v[1]));
            if (is_xh) g_XH[sub][t][b] = h2v[1];
        }

        if (step == 2 * Tt - 1) break;
        __syncthreads();
        if (tid == 0) {
            asm volatile("membar.gl;" ::: "memory");
            atomicAdd(&g_bar, 1u);
            unsigned want = (unsigned)(step + 1) * NBLK;
            unsigned v;
            do {
                asm volatile("ld.acquire.gpu.global.u32 %0,[%1];" : "=r"(v) : "l"(&g_bar));
            } while (v < want);
        }
        __syncthreads();
    }
}

// =====================================================================
// Kernel 3: out = 1.5*u + 0.5*(xh1 + xh2)
// =====================================================================
__global__ __launch_bounds__(256) void epi_kernel(const float* __restrict__ U,
                                                  float* __restrict__ out)
{
    int idx = blockIdx.x * blockDim.x + threadIdx.x;
    if (idx >= Bb * Tt * Dd / 4) return;
    int t = (idx >> 7) & (Tt - 1);
    int b = idx >> 17;
    float s = 0.5f * (g_XH[0][t][b] + g_XH[1][t][b]);
    float4 u = ((const float4*)U)[idx];
    ((float4*)out)[idx] = make_float4(1.5f * u.x + s, 1.5f * u.y + s,
                                      1.5f * u.z + s, 1.5f * u.w + s);
}

extern "C" void kernel_launch(void* const* d_in, const int* in_sizes, int n_in,
                              void* d_out, int out_size) {
    const float* U     = (const float*)d_in[0];
    const float* wih_f = (const float*)d_in[1];
    const float* whh_f = (const float*)d_in[2];
    const float* bih_f = (const float*)d_in[3];
    const float* bhh_f = (const float*)d_in[4];
    const float* wih_b = (const float*)d_in[5];
    const float* whh_b = (const float*)d_in[6];
    const float* bih_b = (const float*)d_in[7];
    const float* bhh_b = (const float*)d_in[8];
    float* out = (float*)d_out;

    const int smem_sz = 65536 + 65536 + (8*8*32 + 32 + NTHR) * 4;
    cudaFuncSetAttribute(rec_kernel, cudaFuncAttributeMaxDynamicSharedMemorySize, smem_sz);

    void* bar_addr = nullptr;
    cudaGetSymbolAddress(&bar_addr, g_bar);
    cudaMemsetAsync(bar_addr, 0, sizeof(unsigned), 0);

    convW_kernel<<<262144 / 256, 256>>>(wih_f, wih_b);
    convU_kernel<<<4194304 / 256, 256>>>(U);
    pre_mma_kernel<<<dim3(32, Tt), 256>>>(bih_f, bhh_f, bih_b, bhh_b);
    rec_kernel<<<NBLK, NTHR, smem_sz>>>(whh_f, whh_b, wih_f, wih_b);
    epi_kernel<<<(Bb * Tt * Dd / 4 + 255) / 256, 256>>>(U, out);
}

// round 11
// speedup vs baseline: 1.2929x; 1.2929x over previous
#include <cuda_runtime.h>
#include <cstdint>
#include <cstddef>
#include <math.h>

#define Bb 32
#define Tt 1024
#define Dd 512
#define Hh 512
#define R4 4096
#define NBLK 128
#define NTHR 256

__device__ float    g_P[(size_t)Tt * R4 * Bb];   // [t][r][b], r = cell*2048+gate*512+j
__device__ float    g_H[2][2][Hh/4][Bb][4];      // [pp][cell][j/4][b][j&3]
__device__ float    g_XH[2][Tt][Bb];
__device__ unsigned g_bar;
__device__ unsigned g_pcnt[Tt];                  // pre-blocks completed per t (target 32)

__device__ __forceinline__ float fsig(float x) {
    x = fminf(fmaxf(x, -30.0f), 30.0f);
    return __fdividef(1.0f, 1.0f + __expf(-x));
}
__device__ __forceinline__ float ftanh(float x) {
    x = fminf(fmaxf(x, -15.0f), 15.0f);
    float e = __expf(2.0f * x);
    return __fdividef(e - 1.0f, e + 1.0f);
}
__device__ __forceinline__ float4 ldcg4(const float4* p) {
    float4 v;
    asm volatile("ld.global.cg.v4.f32 {%0,%1,%2,%3},[%4];"
                 : "=f"(v.x), "=f"(v.y), "=f"(v.z), "=f"(v.w) : "l"(p));
    return v;
}
__device__ __forceinline__ void stcg2(float2* p, float2 v) {
    asm volatile("st.global.cg.v2.f32 [%0],{%1,%2};" :: "l"(p), "f"(v.x), "f"(v.y));
}
__device__ __forceinline__ float ldcg1(const float* p) {
    float v; asm volatile("ld.global.cg.f32 %0,[%1];" : "=f"(v) : "l"(p)); return v;
}

// =====================================================================
// Kernel 1: P[t][r][b] = sum_d U[b][t][d]*Wih[r][d] + bih[r] + bhh[r]
// Double-buffered K-tiles. Runs CONCURRENTLY with rec_kernel; signals
// per-t completion through g_pcnt.
// =====================================================================
__global__ __launch_bounds__(256) void pre_kernel(
    const float* __restrict__ U,
    const float* __restrict__ wih_f, const float* __restrict__ wih_b,
    const float* __restrict__ bih_f, const float* __restrict__ bhh_f,
    const float* __restrict__ bih_b, const float* __restrict__ bhh_b)
{
    __shared__ float Us[2][32][36];
    __shared__ float Ws[2][32][132];

    const int t  = blockIdx.y;
    const int r0 = blockIdx.x * 128;
    const int cb = (r0 >= 2048);
    const float* wih = cb ? wih_b : wih_f;
    const int rbase = r0 - cb * 2048;

    const int tid = threadIdx.x;
    const int b0  = (tid & 7) * 4;
    const int rr0 = ((tid >> 3) & 31) * 4;
    const int bb  = tid >> 3;
    const int kq  = tid & 7;

    const float* Ubase = &U[(size_t)bb * (Tt * Dd) + (size_t)t * Dd + kq * 4];
    const float* Wbase = &wih[(size_t)(rbase + (tid >> 3)) * Dd + kq * 4];

    float acc[4][4];
#pragma unroll
    for (int i = 0; i < 4; ++i)
#pragma unroll
        for (int j = 0; j < 4; ++j) acc[i][j] = 0.0f;

    float4 pu  = *(const float4*)Ubase;
    float4 pw0 = *(const float4*)&Wbase[(size_t)(32 * 0) * Dd];
    float4 pw1 = *(const float4*)&Wbase[(size_t)(32 * 1) * Dd];
    float4 pw2 = *(const float4*)&Wbase[(size_t)(32 * 2) * Dd];
    float4 pw3 = *(const float4*)&Wbase[(size_t)(32 * 3) * Dd];
    {
        Us[0][kq*4+0][bb] = pu.x; Us[0][kq*4+1][bb] = pu.y;
        Us[0][kq*4+2][bb] = pu.z; Us[0][kq*4+3][bb] = pu.w;
        int rr = tid >> 3;
        Ws[0][kq*4+0][rr+ 0] = pw0.x; Ws[0][kq*4+1][rr+ 0] = pw0.y;
        Ws[0][kq*4+2][rr+ 0] = pw0.z; Ws[0][kq*4+3][rr+ 0] = pw0.w;
        Ws[0][kq*4+0][rr+32] = pw1.x; Ws[0][kq*4+1][rr+32] = pw1.y;
        Ws[0][kq*4+2][rr+32] = pw1.z; Ws[0][kq*4+3][rr+32] = pw1.w;
        Ws[0][kq*4+0][rr+64] = pw2.x; Ws[0][kq*4+1][rr+64] = pw2.y;
        Ws[0][kq*4+2][rr+64] = pw2.z; Ws[0][kq*4+3][rr+64] = pw2.w;
        Ws[0][kq*4+0][rr+96] = pw3.x; Ws[0][kq*4+1][rr+96] = pw3.y;
        Ws[0][kq*4+2][rr+96] = pw3.z; Ws[0][kq*4+3][rr+96] = pw3.w;
    }
    __syncthreads();

    for (int kt = 0; kt < 16; ++kt) {
        const int cur = kt & 1;
        if (kt < 15) {
            const int k1 = (kt + 1) * 32;
            pu  = *(const float4*)&Ubase[k1];
            pw0 = *(const float4*)&Wbase[(size_t)(32 * 0) * Dd + k1];
            pw1 = *(const float4*)&Wbase[(size_t)(32 * 1) * Dd + k1];
            pw2 = *(const float4*)&Wbase[(size_t)(32 * 2) * Dd + k1];
            pw3 = *(const float4*)&Wbase[(size_t)(32 * 3) * Dd + k1];
        }
#pragma unroll
        for (int k = 0; k < 32; ++k) {
            float4 ub = *(const float4*)&Us[cur][k][b0];
            float4 wr = *(const float4*)&Ws[cur][k][rr0];
            acc[0][0] += wr.x*ub.x; acc[0][1] += wr.x*ub.y; acc[0][2] += wr.x*ub.z; acc[0][3] += wr.x*ub.w;
            acc[1][0] += wr.y*ub.x; acc[1][1] += wr.y*ub.y; acc[1][2] += wr.y*ub.z; acc[1][3] += wr.y*ub.w;
            acc[2][0] += wr.z*ub.x; acc[2][1] += wr.z*ub.y; acc[2][2] += wr.z*ub.z; acc[2][3] += wr.z*ub.w;
            acc[3][0] += wr.w*ub.x; acc[3][1] += wr.w*ub.y; acc[3][2] += wr.w*ub.z; acc[3][3] += wr.w*ub.w;
        }
        if (kt < 15) {
            const int nxt = cur ^ 1;
            Us[nxt][kq*4+0][bb] = pu.x; Us[nxt][kq*4+1][bb] = pu.y;
            Us[nxt][kq*4+2][bb] = pu.z; Us[nxt][kq*4+3][bb] = pu.w;
            int rr = tid >> 3;
            Ws[nxt][kq*4+0][rr+ 0] = pw0.x; Ws[nxt][kq*4+1][rr+ 0] = pw0.y;
            Ws[nxt][kq*4+2][rr+ 0] = pw0.z; Ws[nxt][kq*4+3][rr+ 0] = pw0.w;
            Ws[nxt][kq*4+0][rr+32] = pw1.x; Ws[nxt][kq*4+1][rr+32] = pw1.y;
            Ws[nxt][kq*4+2][rr+32] = pw1.z; Ws[nxt][kq*4+3][rr+32] = pw1.w;
            Ws[nxt][kq*4+0][rr+64] = pw2.x; Ws[nxt][kq*4+1][rr+64] = pw2.y;
            Ws[nxt][kq*4+2][rr+64] = pw2.z; Ws[nxt][kq*4+3][rr+64] = pw2.w;
            Ws[nxt][kq*4+0][rr+96] = pw3.x; Ws[nxt][kq*4+1][rr+96] = pw3.y;
            Ws[nxt][kq*4+2][rr+96] = pw3.z; Ws[nxt][kq*4+3][rr+96] = pw3.w;
            __syncthreads();
        }
    }
#pragma unroll
    for (int i = 0; i < 4; ++i) {
        int rw = rbase + rr0 + i;
        float bias = cb ? (bih_b[rw] + bhh_b[rw]) : (bih_f[rw] + bhh_f[rw]);
        float4 o = make_float4(acc[i][0]+bias, acc[i][1]+bias, acc[i][2]+bias, acc[i][3]+bias);
        *(float4*)&g_P[((size_t)t * R4 + (size_t)(r0 + rr0 + i)) * Bb + b0] = o;
    }
    // publish: this block's slice of P[t] is globally visible
    __threadfence();
    __syncthreads();
    if (tid == 0) atomicAdd(&g_pcnt[t], 1u);
}

// =====================================================================
// Kernel 2: persistent recurrence, runs CONCURRENTLY with pre_kernel.
// Waits on g_pcnt[t]==32 before consuming P[t].
// =====================================================================
__global__ void __launch_bounds__(NTHR, 1) rec_kernel(
    const float* __restrict__ whh_f, const float* __restrict__ whh_b,
    const float* __restrict__ wih_f, const float* __restrict__ wih_b)
{
    extern __shared__ char smraw[];
    float*  ws   = (float*)smraw;                 // [32 rows][512]  row = p*8+u*4+gate
    float4* hs   = (float4*)(smraw + 65536);      // [128 kq][32 b]
    float*  redA = (float*)(smraw + 131072);      // [8 w][8 q][32 b]
    float*  rsum = redA + 8*8*32;                 // [32]
    float*  red  = rsum + 32;                     // [256]

    const int tid  = threadIdx.x;
    const int w    = tid >> 5;
    const int p    = w & 3;
    const int kh   = w >> 2;
    const int b    = tid & 31;
    const int cell = blockIdx.x >> 6;
    const int g    = blockIdx.x & 63;
    const int jA   = g * 8 + 2 * p;

    const float* whh = cell ? whh_b : whh_f;
    const float* wih = cell ? wih_b : wih_f;

    for (int idx = tid * 4; idx < 32 * 512; idx += NTHR * 4) {
        int rl = idx >> 9, k = idx & 511;
        int p_ = rl >> 3, q = rl & 7, u = q >> 2, gate = q & 3;
        int grow = gate * 512 + g * 8 + 2 * p_ + u;
        *(float4*)&ws[idx] = *(const float4*)&whh[(size_t)grow * 512 + k];
    }
    {   // rowsums of Wih (sub-step-2 scalar-broadcast projection)
        int rl = tid & 31, part = tid >> 5;
        int p_ = rl >> 3, q = rl & 7, u = q >> 2, gate = q & 3;
        int grow = gate * 512 + g * 8 + 2 * p_ + u;
        float s = 0.0f;
        const float* pp = &wih[(size_t)grow * 512 + part * 64];
#pragma unroll 4
        for (int k = 0; k < 64; k += 4) {
            float4 v = *(const float4*)&pp[k];
            s += v.x + v.y + v.z + v.w;
        }
        red[tid] = s;
    }
    __syncthreads();
    if (tid < 32) {
        float s = 0.0f;
#pragma unroll
        for (int q = 0; q < 8; ++q) s += red[tid + 32 * q];
        rsum[tid] = s;
    }
    __syncthreads();
    float rs[8];
#pragma unroll
    for (int q = 0; q < 8; ++q) rs[q] = rsum[p * 8 + q];

    float cst[2] = {0.0f, 0.0f};
    const float4* wr4 = (const float4*)(ws + (p * 8) * 512);
    const bool is_xh = (cell == 1 && jA + 1 == Hh - 1);

    for (int step = 0; step < 2 * Tt; ++step) {
        const int t = step >> 1, sub = step & 1;
        const int rbuf = step & 1, wbuf = rbuf ^ 1;

        // wait until all 32 producer blocks of P[t] have published
        if (sub == 0) {
            if (tid == 0) {
                unsigned v;
                do {
                    asm volatile("ld.acquire.gpu.global.u32 %0,[%1];"
                                 : "=r"(v) : "l"(&g_pcnt[t]));
                } while (v < 32u);
            }
            __syncthreads();
        }

        float pv[8];
        if (kh == 0) {
            const float* Pt = g_P + ((size_t)t * R4 + (size_t)cell * 2048) * Bb;
#pragma unroll
            for (int q = 0; q < 8; ++q) {
                int u = q >> 2, gate = q & 3;
                pv[q] = ldcg1(&Pt[(size_t)(gate * 512 + jA + u) * Bb + b]);
            }
        }
        float xh = (sub && kh == 0) ? ldcg1(&g_H[rbuf][1][(Hh - 1) >> 2][b][3]) : 0.0f;

        if (step == 0) {
            float4 z = make_float4(0.f, 0.f, 0.f, 0.f);
            for (int i = tid; i < 128 * 32; i += NTHR) hs[i] = z;
        } else {
            const float4* src = (const float4*)&g_H[rbuf][cell][0][0][0];
            for (int i = tid; i < 128 * 32; i += NTHR) hs[i] = ldcg4(&src[i]);
        }
        __syncthreads();

        float acc[8];
#pragma unroll
        for (int q = 0; q < 8; ++q) acc[q] = 0.0f;
        const float4* hb = hs + b;
#pragma unroll 4
        for (int kq = kh * 64; kq < kh * 64 + 64; ++kq) {
            float4 hv = hb[kq * 32];
#pragma unroll
            for (int q = 0; q < 8; ++q) {
                float4 wv = wr4[q * 128 + kq];
                acc[q] += wv.x * hv.x;
                acc[q] += wv.y * hv.y;
                acc[q] += wv.z * hv.z;
                acc[q] += wv.w * hv.w;
            }
        }
#pragma unroll
        for (int q = 0; q < 8; ++q) redA[(w * 8 + q) * 32 + b] = acc[q];
        __syncthreads();

        if (kh == 0) {
            float h2v[2];
#pragma unroll
            for (int u = 0; u < 2; ++u) {
#pragma unroll
                for (int q = 0; q < 4; ++q) {
                    int qq = u * 4 + q;
                    acc[qq] += redA[((w + 4) * 8 + qq) * 32 + b];
                    acc[qq] += pv[qq] + xh * rs[qq];
                }
                float iv = acc[u*4+0], fv = acc[u*4+1], gv = acc[u*4+2], ov = acc[u*4+3];
                cst[u] = fsig(fv) * cst[u] + fsig(iv) * ftanh(gv);
                h2v[u] = fsig(ov) * ftanh(cst[u]);
            }
            stcg2((float2*)&g_H[wbuf][cell][jA >> 2][b][jA & 3],
                  make_float2(h2v[0], h2v[1]));
            if (is_xh) g_XH[sub][t][b] = h2v[1];
        }

        if (step == 2 * Tt - 1) break;
        __syncthreads();
        if (tid == 0) {
            asm volatile("membar.gl;" ::: "memory");
            atomicAdd(&g_bar, 1u);
            unsigned want = (unsigned)(step + 1) * NBLK;
            unsigned v;
            do {
                asm volatile("ld.acquire.gpu.global.u32 %0,[%1];" : "=r"(v) : "l"(&g_bar));
            } while (v < want);
        }
        __syncthreads();
    }
}

// =====================================================================
// Kernel 3: out = 1.5*u + 0.5*(xh1 + xh2)
// =====================================================================
__global__ __launch_bounds__(256) void epi_kernel(const float* __restrict__ U,
                                                  float* __restrict__ out)
{
    int idx = blockIdx.x * blockDim.x + threadIdx.x;
    if (idx >= Bb * Tt * Dd / 4) return;
    int t = (idx >> 7) & (Tt - 1);
    int b = idx >> 17;
    float s = 0.5f * (g_XH[0][t][b] + g_XH[1][t][b]);
    float4 u = ((const float4*)U)[idx];
    ((float4*)out)[idx] = make_float4(1.5f * u.x + s, 1.5f * u.y + s,
                                      1.5f * u.z + s, 1.5f * u.w + s);
}

extern "C" void kernel_launch(void* const* d_in, const int* in_sizes, int n_in,
                              void* d_out, int out_size) {
    const float* U     = (const float*)d_in[0];
    const float* wih_f = (const float*)d_in[1];
    const float* whh_f = (const float*)d_in[2];
    const float* bih_f = (const float*)d_in[3];
    const float* bhh_f = (const float*)d_in[4];
    const float* wih_b = (const float*)d_in[5];
    const float* whh_b = (const float*)d_in[6];
    const float* bih_b = (const float*)d_in[7];
    const float* bhh_b = (const float*)d_in[8];
    float* out = (float*)d_out;

    const int smem_sz = 65536 + 65536 + (8*8*32 + 32 + NTHR) * 4;
    cudaFuncSetAttribute(rec_kernel, cudaFuncAttributeMaxDynamicSharedMemorySize, smem_sz);

    // one-time stream/event creation (host objects, no device memory)
    static cudaStream_t s2 = nullptr;
    static cudaEvent_t ev_fork = nullptr, ev_join = nullptr;
    if (s2 == nullptr) {
        cudaStreamCreateWithFlags(&s2, cudaStreamNonBlocking);
        cudaEventCreateWithFlags(&ev_fork, cudaEventDisableTiming);
        cudaEventCreateWithFlags(&ev_join, cudaEventDisableTiming);
    }

    void* bar_addr = nullptr;
    void* pcnt_addr = nullptr;
    cudaGetSymbolAddress(&bar_addr, g_bar);
    cudaGetSymbolAddress(&pcnt_addr, g_pcnt);
    cudaMemsetAsync(bar_addr, 0, sizeof(unsigned), 0);
    cudaMemsetAsync(pcnt_addr, 0, Tt * sizeof(unsigned), 0);

    // fork: pre on s2, rec on default stream — they run concurrently;
    // rec consumes P[t] gated by g_pcnt[t].
    cudaEventRecord(ev_fork, 0);
    cudaStreamWaitEvent(s2, ev_fork, 0);
    pre_kernel<<<dim3(32, Tt), 256, 0, s2>>>(U, wih_f, wih_b, bih_f, bhh_f, bih_b, bhh_b);
    cudaEventRecord(ev_join, s2);

    rec_kernel<<<NBLK, NTHR, smem_sz>>>(whh_f, whh_b, wih_f, wih_b);

    // join pre back before epilogue
    cudaStreamWaitEvent(0, ev_join, 0);
    epi_kernel<<<(Bb * Tt * Dd / 4 + 255) / 256, 256>>>(U, out);
}